// round 14
// baseline (speedup 1.0000x reference)
#include <cuda_runtime.h>
#include <cstdint>

#define S_LEN 2048
#define BATCH 2
#define NH    16
#define DH    64
#define HID   1024
#define MROWS 4096

// -------- scratch (static __device__; no allocations allowed) --------
__device__ float g_xt  [MROWS * HID];   // x, A-frag layout, tf32
__device__ float g_Q   [MROWS * HID];   // Q row-major, scaled by 0.125*log2e, tf32
__device__ float g_Kf  [MROWS * HID];   // K, score-B-frag layout, tf32
__device__ float g_Vf  [MROWS * HID];   // V, PV-B-frag layout, tf32
__device__ float g_ctxf[MROWS * HID];   // ctx, A-frag layout, tf32
__device__ float g_Wqf [HID * HID];     // weights, B-frag layout, tf32
__device__ float g_Wkf [HID * HID];
__device__ float g_Wvf [HID * HID];
__device__ float g_Wof [HID * HID];

// ---------------------------------------------------------------------------
// helpers
// ---------------------------------------------------------------------------
__device__ __forceinline__ unsigned f2tf(float x) {
    unsigned r;
    asm("cvt.rna.tf32.f32 %0, %1;" : "=r"(r) : "f"(x));
    return r;
}
__device__ __forceinline__ float tfr(float x) {
    return __uint_as_float(f2tf(x));
}
__device__ __forceinline__ float ex2(float x) {
    float r;
    asm("ex2.approx.f32 %0, %1;" : "=f"(r) : "f"(x));
    return r;
}
__device__ __forceinline__ void mma8(float* c, const unsigned* a, const unsigned* b) {
    asm volatile(
        "mma.sync.aligned.m16n8k8.row.col.f32.tf32.tf32.f32 "
        "{%0,%1,%2,%3}, {%4,%5,%6,%7}, {%8,%9}, {%0,%1,%2,%3};"
        : "+f"(c[0]), "+f"(c[1]), "+f"(c[2]), "+f"(c[3])
        : "r"(a[0]), "r"(a[1]), "r"(a[2]), "r"(a[3]), "r"(b[0]), "r"(b[1]));
}
__device__ __forceinline__ uint32_t smem_u32(const void* p) {
    uint32_t r;
    asm("{ .reg .u64 t; cvta.to.shared.u64 t, %1; cvt.u32.u64 %0, t; }"
        : "=r"(r) : "l"(p));
    return r;
}
#define CP_ASYNC16(saddr, gptr) \
    asm volatile("cp.async.cg.shared.global [%0], [%1], 16;" \
                 :: "r"((uint32_t)(saddr)), "l"(gptr) : "memory")
#define CP_COMMIT() asm volatile("cp.async.commit_group;" ::: "memory")
#define CP_WAIT0()  asm volatile("cp.async.wait_group 0;" ::: "memory")

// ---------------------------------------------------------------------------
// Fragment-layout index helpers (word offsets) — validated in R13
// ---------------------------------------------------------------------------
__device__ __forceinline__ int afrag_idx(int r, int k) {
    int lane = ((r & 7) << 2) | (k & 3);
    int word = ((r >> 3) & 1) | (((k >> 2) & 1) << 1);
    int slot = (((((k >> 3) & 3) << 3) | ((r >> 4) & 7)) << 5) | lane;
    return ((((r >> 7) << 5) | (k >> 5)) << 12) + slot * 4 + word;
}
__device__ __forceinline__ int kfrag_idx(int r, int h, int d) {
    int s = r & 2047, b = r >> 11;
    int lane = ((s & 7) << 2) | (d & 3);
    int word = (d >> 2) & 1;
    int slot = ((((d >> 3) << 3) | ((s >> 3) & 7)) << 5) | lane;
    return ((((b * NH + h) << 5) | (s >> 6)) << 12) + slot * 2 + word;
}
__device__ __forceinline__ int vfrag_idx(int r, int h, int d) {
    int s = r & 2047, b = r >> 11;
    int lane = ((d & 7) << 2) | (s & 3);
    int word = (s >> 2) & 1;
    int slot = (((((s >> 3) & 7) << 3) | (d >> 3)) << 5) | lane;
    return ((((b * NH + h) << 5) | (s >> 6)) << 12) + slot * 2 + word;
}

// ===========================================================================
// One fused layout-transform kernel (round to tf32 while scattering).
// Block ranges: [0,4096) x -> A-frag; then 4 x 2048 blocks for the weights.
// ===========================================================================
__global__ __launch_bounds__(256) void cvt_all(
    const float* __restrict__ x,
    const float* __restrict__ Wq, const float* __restrict__ Wk,
    const float* __restrict__ Wv, const float* __restrict__ Wo)
{
    int blk = blockIdx.x;
    if (blk < 4096) {
        int id = blk * 256 + threadIdx.x;             // uint4 id
        int lane = id & 31;
        int t2   = (id >> 5) & 31;
        int bb   = id >> 10;
        int r = ((bb >> 5) << 7) + ((t2 & 7) << 4) + (lane >> 2);
        int k = ((bb & 31) << 5) + ((t2 >> 3) << 3) + (lane & 3);
        const float* p = x + (long)r * HID + k;
        ((float4*)g_xt)[id] = make_float4(tfr(p[0]), tfr(p[8 * HID]),
                                          tfr(p[4]), tfr(p[8 * HID + 4]));
    } else {
        int wsel = (blk - 4096) >> 11;                // 0..3
        int id = ((blk - 4096) & 2047) * 256 + threadIdx.x;   // uint2 id
        const float* W; float2* dst; long ts; int rs, cm;
        if (wsel == 0)      { W = Wq; dst = (float2*)g_Wqf; ts = (long)HID*DH; rs = DH;  cm = 63; }
        else if (wsel == 1) { W = Wk; dst = (float2*)g_Wkf; ts = (long)HID*DH; rs = DH;  cm = 63; }
        else if (wsel == 2) { W = Wv; dst = (float2*)g_Wvf; ts = (long)HID*DH; rs = DH;  cm = 63; }
        else                { W = Wo; dst = (float2*)g_Wof; ts = 0L;           rs = HID; cm = 1023; }
        int lane = id & 31;
        int t2   = (id >> 5) & 63;
        int bb   = id >> 11;
        int j = ((bb >> 5) << 7) + ((t2 & 15) << 3) + (lane >> 2);
        int k = ((bb & 31) << 5) + ((t2 >> 4) << 3) + (lane & 3);
        const float* p = W + (long)(j >> 6) * ts + (long)k * rs + (j & cm);
        dst[id] = make_float2(tfr(p[0]), tfr(p[(long)4 * rs]));
    }
}

// ===========================================================================
// tf32 GEMM, fragment-major operands, cp.async identity staging (R13 WIN).
// ===========================================================================
#define GE_SMEM (16384 * 4)

__device__ __forceinline__ void gemm_fr(
    const float* __restrict__ Af, const float* __restrict__ Bf,
    const float* __restrict__ bias, float* __restrict__ Crow,
    int mode, float scale)
{
    extern __shared__ unsigned gsm[];
    const uint32_t sb = smem_u32(gsm);
    const int MB = blockIdx.y;
    const int JB = blockIdx.x;
    const int tid  = threadIdx.x;
    const int lane = tid & 31;
    const int w    = tid >> 5;
    const int wmt = (w >> 2) * 4;
    const int wnt = (w & 3) * 4;
    const int lr = lane >> 2;
    const int lc = lane & 3;

    float acc[4][4][4];
    #pragma unroll
    for (int i = 0; i < 4; ++i)
        #pragma unroll
        for (int j = 0; j < 4; ++j)
            #pragma unroll
            for (int k = 0; k < 4; ++k) acc[i][j][k] = 0.f;

    #define GSTAGE(KC, S) do {                                                \
        const float4* Ab_ = (const float4*)(Af + ((long)(MB * 32 + (KC)) << 12)); \
        const float4* Bb_ = (const float4*)(Bf + ((long)(JB * 32 + (KC)) << 12)); \
        uint32_t ad_ = sb + ((S) ? 16384u : 0u);                              \
        uint32_t bd_ = sb + 32768u + ((S) ? 16384u : 0u);                     \
        _Pragma("unroll")                                                     \
        for (int i_ = 0; i_ < 4; ++i_) {                                      \
            int lin_ = tid + i_ * 256;                                        \
            CP_ASYNC16(ad_ + lin_ * 16, Ab_ + lin_);                          \
            CP_ASYNC16(bd_ + lin_ * 16, Bb_ + lin_);                          \
        }                                                                     \
    } while (0)

    GSTAGE(0, 0);
    CP_COMMIT();

    for (int c = 0; c < 32; ++c) {
        CP_WAIT0();
        __syncthreads();
        if (c + 1 < 32) {
            GSTAGE(c + 1, (c + 1) & 1);
            CP_COMMIT();
        }
        const unsigned* Ac = gsm + ((c & 1) ? 4096 : 0);
        const unsigned* Bc = gsm + 8192 + ((c & 1) ? 4096 : 0);

        #pragma unroll
        for (int ks = 0; ks < 4; ++ks) {
            uint4 a[4];
            uint2 b[4];
            #pragma unroll
            for (int mt = 0; mt < 4; ++mt)
                a[mt] = *(const uint4*)&Ac[(((ks * 8 + wmt + mt) << 5) | lane) * 4];
            #pragma unroll
            for (int nt = 0; nt < 4; ++nt)
                b[nt] = *(const uint2*)&Bc[(((ks * 16 + wnt + nt) << 5) | lane) * 2];
            #pragma unroll
            for (int mt = 0; mt < 4; ++mt)
                #pragma unroll
                for (int nt = 0; nt < 4; ++nt)
                    mma8(acc[mt][nt], &a[mt].x, &b[nt].x);
        }
    }

    #pragma unroll
    for (int mt = 0; mt < 4; ++mt) {
        int r0 = MB * 128 + (wmt + mt) * 16 + lr;
        #pragma unroll
        for (int nt = 0; nt < 4; ++nt) {
            int cg = JB * 128 + (wnt + nt) * 8 + lc * 2;
            float b0 = bias[cg], b1 = bias[cg + 1];
            float e0 = acc[mt][nt][0] + b0;
            float e1 = acc[mt][nt][1] + b1;
            float e2 = acc[mt][nt][2] + b0;
            float e3 = acc[mt][nt][3] + b1;
            if (mode == 0) {
                *(float2*)(Crow + (long)r0 * HID + cg) =
                    make_float2(tfr(e0 * scale), tfr(e1 * scale));
                *(float2*)(Crow + (long)(r0 + 8) * HID + cg) =
                    make_float2(tfr(e2 * scale), tfr(e3 * scale));
            } else if (mode == 1) {
                int h = cg >> 6, d = cg & 63;
                g_Kf[kfrag_idx(r0, h, d)]         = tfr(e0);
                g_Kf[kfrag_idx(r0, h, d + 1)]     = tfr(e1);
                g_Kf[kfrag_idx(r0 + 8, h, d)]     = tfr(e2);
                g_Kf[kfrag_idx(r0 + 8, h, d + 1)] = tfr(e3);
            } else if (mode == 2) {
                int h = cg >> 6, d = cg & 63;
                g_Vf[vfrag_idx(r0, h, d)]         = tfr(e0);
                g_Vf[vfrag_idx(r0, h, d + 1)]     = tfr(e1);
                g_Vf[vfrag_idx(r0 + 8, h, d)]     = tfr(e2);
                g_Vf[vfrag_idx(r0 + 8, h, d + 1)] = tfr(e3);
            } else {
                *(float2*)(Crow + (long)r0 * HID + cg) = make_float2(e0, e1);
                *(float2*)(Crow + (long)(r0 + 8) * HID + cg) = make_float2(e2, e3);
            }
        }
    }
}

__global__ __launch_bounds__(256, 2) void gemm_qkv(
    const float* __restrict__ bq, const float* __restrict__ bk,
    const float* __restrict__ bv)
{
    const float LOG2E = 1.4426950408889634f;
    if (blockIdx.z == 0)
        gemm_fr(g_xt, g_Wqf, bq, g_Q, 0, 0.125f * LOG2E);
    else if (blockIdx.z == 1)
        gemm_fr(g_xt, g_Wkf, bk, (float*)0, 1, 1.f);
    else
        gemm_fr(g_xt, g_Wvf, bv, (float*)0, 2, 1.f);
}

__global__ __launch_bounds__(256, 2) void gemm_out(
    const float* __restrict__ bo, float* __restrict__ out)
{
    gemm_fr(g_ctxf, g_Wof, bo, out, 3, 1.f);
}

// ===========================================================================
// Flash attention v6: 4 warps x 32 q-rows (2 m-tiles per warp).
// Each K/V b-frag LDS.64 now feeds TWO mma -> smem B traffic halved vs v5;
// flips the kernel from smem-crossbar-bound to tensor-bound.
// 128 threads, 128 q-rows/CTA, 64-key tiles, double-buffered cp.async.
// smem: Kb 2x4096 | Vb 2x4096 | Ps 128x68 words
// ===========================================================================
#define FL_PS 16384
#define ATT_SMEM ((16384 + 128 * 68) * 4)   // 100352 bytes

__global__ __launch_bounds__(128, 2) void flash_v6()
{
    extern __shared__ unsigned smu[];
    unsigned* Ps = smu + FL_PS;
    const uint32_t sbase = smem_u32(smu);

    const int bh = blockIdx.y;               // b*NH + h
    const int b  = bh >> 4;
    const int h  = bh & 15;
    const int m0 = blockIdx.x << 7;
    const int tid  = threadIdx.x;
    const int lane = tid & 31;
    const int w    = tid >> 5;               // 0..3
    const int lr = lane >> 2;
    const int lc = lane & 3;
    // warp w owns rows w*32 .. w*32+31 (m-tiles mt=0,1)
    const int pr00 = w * 32 + lr;            // mt0 rows: pr00, pr00+8
    const int pr10 = pr00 + 16;              // mt1 rows: pr10, pr10+8

    // Q fragments (row-major gmem; already scaled by 0.125*log2e, tf32)
    unsigned q[2][8][4];
    #pragma unroll
    for (int mt = 0; mt < 2; ++mt) {
        const unsigned* Qg = (const unsigned*)
            (g_Q + ((long)b * S_LEN + m0 + (mt ? pr10 : pr00)) * HID + h * DH);
        #pragma unroll
        for (int ks = 0; ks < 8; ++ks) {
            q[mt][ks][0] = Qg[ks * 8 + lc];
            q[mt][ks][1] = Qg[8 * HID + ks * 8 + lc];
            q[mt][ks][2] = Qg[ks * 8 + 4 + lc];
            q[mt][ks][3] = Qg[8 * HID + ks * 8 + 4 + lc];
        }
    }

    float o[2][8][4];
    #pragma unroll
    for (int mt = 0; mt < 2; ++mt)
        #pragma unroll
        for (int i = 0; i < 8; ++i)
            #pragma unroll
            for (int j = 0; j < 4; ++j) o[mt][i][j] = 0.f;
    float li[4] = {0.f, 0.f, 0.f, 0.f};      // rows pr00, pr00+8, pr10, pr10+8

    // identity staging: 1024 + 1024 16B chunks over 128 threads
    #define FSTAGE(T, S) do {                                                 \
        const float4* Kt_ = (const float4*)(g_Kf + ((long)(bh * 32 + (T)) << 12)); \
        const float4* Vt_ = (const float4*)(g_Vf + ((long)(bh * 32 + (T)) << 12)); \
        uint32_t kd_ = sbase + ((S) ? 16384u : 0u);                           \
        uint32_t vd_ = sbase + 32768u + ((S) ? 16384u : 0u);                  \
        _Pragma("unroll")                                                     \
        for (int i_ = 0; i_ < 8; ++i_) {                                      \
            int lin_ = tid + i_ * 128;                                        \
            CP_ASYNC16(kd_ + lin_ * 16, Kt_ + lin_);                          \
            CP_ASYNC16(vd_ + lin_ * 16, Vt_ + lin_);                          \
        }                                                                     \
    } while (0)

    FSTAGE(0, 0);
    CP_COMMIT();

    for (int t = 0; t < S_LEN / 64; ++t) {
        const int s = t & 1;
        CP_WAIT0();
        __syncthreads();
        if (t + 1 < S_LEN / 64) {
            FSTAGE(t + 1, s ^ 1);
            CP_COMMIT();
        }
        const unsigned* Kb = smu + (s ? 4096 : 0);
        const unsigned* Vb = smu + 8192 + (s ? 4096 : 0);

        // scores (log2 domain): one b-frag load feeds both m-tiles
        float sc[2][8][4];
        #pragma unroll
        for (int mt = 0; mt < 2; ++mt)
            #pragma unroll
            for (int nt = 0; nt < 8; ++nt)
                #pragma unroll
                for (int j = 0; j < 4; ++j) sc[mt][nt][j] = 0.f;
        #pragma unroll
        for (int ks = 0; ks < 8; ++ks) {
            #pragma unroll
            for (int nt = 0; nt < 8; ++nt) {
                uint2 bf = *(const uint2*)&Kb[(((ks * 8 + nt) << 5) | lane) * 2];
                mma8(sc[0][nt], q[0][ks], &bf.x);
                mma8(sc[1][nt], q[1][ks], &bf.x);
            }
        }

        // softmax numerator: p = exp2(score)
        float rs[4] = {0.f, 0.f, 0.f, 0.f};
        #pragma unroll
        for (int mt = 0; mt < 2; ++mt) {
            int r0 = mt ? pr10 : pr00;
            #pragma unroll
            for (int nt = 0; nt < 8; ++nt) {
                sc[mt][nt][0] = ex2(sc[mt][nt][0]); rs[mt * 2]     += sc[mt][nt][0];
                sc[mt][nt][1] = ex2(sc[mt][nt][1]); rs[mt * 2]     += sc[mt][nt][1];
                sc[mt][nt][2] = ex2(sc[mt][nt][2]); rs[mt * 2 + 1] += sc[mt][nt][2];
                sc[mt][nt][3] = ex2(sc[mt][nt][3]); rs[mt * 2 + 1] += sc[mt][nt][3];
                *(uint2*)&Ps[r0 * 68 + nt * 8 + lc * 2] =
                    make_uint2(f2tf(sc[mt][nt][0]), f2tf(sc[mt][nt][1]));
                *(uint2*)&Ps[(r0 + 8) * 68 + nt * 8 + lc * 2] =
                    make_uint2(f2tf(sc[mt][nt][2]), f2tf(sc[mt][nt][3]));
            }
        }
        #pragma unroll
        for (int i = 0; i < 4; ++i) {
            rs[i] += __shfl_xor_sync(0xffffffffu, rs[i], 1);
            rs[i] += __shfl_xor_sync(0xffffffffu, rs[i], 2);
            li[i] += rs[i];
        }
        __syncwarp();

        // PV: O += P V ; b-frag shared across both m-tiles
        #pragma unroll
        for (int ks = 0; ks < 8; ++ks) {
            int kb = ks * 8;
            unsigned a[2][4];
            a[0][0] = Ps[pr00 * 68 + kb + lc];
            a[0][1] = Ps[(pr00 + 8) * 68 + kb + lc];
            a[0][2] = Ps[pr00 * 68 + kb + 4 + lc];
            a[0][3] = Ps[(pr00 + 8) * 68 + kb + 4 + lc];
            a[1][0] = Ps[pr10 * 68 + kb + lc];
            a[1][1] = Ps[(pr10 + 8) * 68 + kb + lc];
            a[1][2] = Ps[pr10 * 68 + kb + 4 + lc];
            a[1][3] = Ps[(pr10 + 8) * 68 + kb + 4 + lc];
            #pragma unroll
            for (int nt = 0; nt < 8; ++nt) {
                uint2 bf = *(const uint2*)&Vb[(((ks * 8 + nt) << 5) | lane) * 2];
                mma8(o[0][nt], a[0], &bf.x);
                mma8(o[1][nt], a[1], &bf.x);
            }
        }
    }

    // normalize, write ctx in A-frag layout (tf32) for the out-projection
    #pragma unroll
    for (int mt = 0; mt < 2; ++mt) {
        float inv0 = 1.f / li[mt * 2];
        float inv1 = 1.f / li[mt * 2 + 1];
        int rg0 = b * S_LEN + m0 + (mt ? pr10 : pr00);
        #pragma unroll
        for (int nt = 0; nt < 8; ++nt) {
            int cg = h * 64 + nt * 8 + lc * 2;
            g_ctxf[afrag_idx(rg0, cg)]         = tfr(o[mt][nt][0] * inv0);
            g_ctxf[afrag_idx(rg0, cg + 1)]     = tfr(o[mt][nt][1] * inv0);
            g_ctxf[afrag_idx(rg0 + 8, cg)]     = tfr(o[mt][nt][2] * inv1);
            g_ctxf[afrag_idx(rg0 + 8, cg + 1)] = tfr(o[mt][nt][3] * inv1);
        }
    }
}

// ===========================================================================
// Launch
// ===========================================================================
extern "C" void kernel_launch(void* const* d_in, const int* in_sizes, int n_in,
                              void* d_out, int out_size)
{
    (void)in_sizes; (void)n_in; (void)out_size;
    const float* x  = (const float*)d_in[0];
    const float* Wq = (const float*)d_in[1];
    const float* bq = (const float*)d_in[2];
    const float* Wk = (const float*)d_in[3];
    const float* bk = (const float*)d_in[4];
    const float* Wv = (const float*)d_in[5];
    const float* bv = (const float*)d_in[6];
    const float* Wo = (const float*)d_in[7];
    const float* bo = (const float*)d_in[8];
    float* out = (float*)d_out;

    cudaFuncSetAttribute(gemm_qkv,
                         cudaFuncAttributeMaxDynamicSharedMemorySize, GE_SMEM);
    cudaFuncSetAttribute(gemm_out,
                         cudaFuncAttributeMaxDynamicSharedMemorySize, GE_SMEM);
    cudaFuncSetAttribute(flash_v6,
                         cudaFuncAttributeMaxDynamicSharedMemorySize, ATT_SMEM);

    // one fused layout-transform launch (x + 4 weights)
    cvt_all<<<4096 + 4 * 2048, 256>>>(x, Wq, Wk, Wv, Wo);

    // QKV projections (z: 0=Q row-major scaled, 1=K frag, 2=V frag)
    gemm_qkv<<<dim3(HID / 128, MROWS / 128, 3), 256, GE_SMEM>>>(bq, bk, bv);

    flash_v6<<<dim3(S_LEN / 128, BATCH * NH), 128, ATT_SMEM>>>();

    // output projection: ctx @ Wo + bo
    gemm_out<<<dim3(HID / 128, MROWS / 128), 256, GE_SMEM>>>(bo, out);
}

// round 15
// speedup vs baseline: 1.4519x; 1.4519x over previous
#include <cuda_runtime.h>
#include <cstdint>

#define S_LEN 2048
#define BATCH 2
#define NH    16
#define DH    64
#define HID   1024
#define MROWS 4096

// -------- scratch (static __device__; no allocations allowed) --------
__device__ float g_xt  [MROWS * HID];   // x, A-frag layout, tf32
__device__ float g_Q   [MROWS * HID];   // Q row-major, scaled by 0.125*log2e, tf32
__device__ float g_Kf  [MROWS * HID];   // K, score-B-frag layout, tf32
__device__ float g_Vf  [MROWS * HID];   // V, PV-B-frag layout, tf32
__device__ float g_ctxf[MROWS * HID];   // ctx, A-frag layout, tf32
__device__ float g_Wqf [HID * HID];     // weights, B-frag layout, tf32
__device__ float g_Wkf [HID * HID];
__device__ float g_Wvf [HID * HID];
__device__ float g_Wof [HID * HID];

// ---------------------------------------------------------------------------
// helpers
// ---------------------------------------------------------------------------
__device__ __forceinline__ unsigned f2tf(float x) {
    unsigned r;
    asm("cvt.rna.tf32.f32 %0, %1;" : "=r"(r) : "f"(x));
    return r;
}
__device__ __forceinline__ float tfr(float x) {
    return __uint_as_float(f2tf(x));
}
__device__ __forceinline__ float ex2(float x) {
    float r;
    asm("ex2.approx.f32 %0, %1;" : "=f"(r) : "f"(x));
    return r;
}
__device__ __forceinline__ void mma8(float* c, const unsigned* a, const unsigned* b) {
    asm volatile(
        "mma.sync.aligned.m16n8k8.row.col.f32.tf32.tf32.f32 "
        "{%0,%1,%2,%3}, {%4,%5,%6,%7}, {%8,%9}, {%0,%1,%2,%3};"
        : "+f"(c[0]), "+f"(c[1]), "+f"(c[2]), "+f"(c[3])
        : "r"(a[0]), "r"(a[1]), "r"(a[2]), "r"(a[3]), "r"(b[0]), "r"(b[1]));
}
__device__ __forceinline__ uint32_t smem_u32(const void* p) {
    uint32_t r;
    asm("{ .reg .u64 t; cvta.to.shared.u64 t, %1; cvt.u32.u64 %0, t; }"
        : "=r"(r) : "l"(p));
    return r;
}
#define CP_ASYNC16(saddr, gptr) \
    asm volatile("cp.async.cg.shared.global [%0], [%1], 16;" \
                 :: "r"((uint32_t)(saddr)), "l"(gptr) : "memory")
#define CP_COMMIT() asm volatile("cp.async.commit_group;" ::: "memory")
#define CP_WAIT0()  asm volatile("cp.async.wait_group 0;" ::: "memory")
#define CP_WAIT1()  asm volatile("cp.async.wait_group 1;" ::: "memory")

// ---------------------------------------------------------------------------
// Fragment-layout index helpers (word offsets) — validated in R13
// ---------------------------------------------------------------------------
__device__ __forceinline__ int afrag_idx(int r, int k) {
    int lane = ((r & 7) << 2) | (k & 3);
    int word = ((r >> 3) & 1) | (((k >> 2) & 1) << 1);
    int slot = (((((k >> 3) & 3) << 3) | ((r >> 4) & 7)) << 5) | lane;
    return ((((r >> 7) << 5) | (k >> 5)) << 12) + slot * 4 + word;
}
__device__ __forceinline__ int kfrag_idx(int r, int h, int d) {
    int s = r & 2047, b = r >> 11;
    int lane = ((s & 7) << 2) | (d & 3);
    int word = (d >> 2) & 1;
    int slot = ((((d >> 3) << 3) | ((s >> 3) & 7)) << 5) | lane;
    return ((((b * NH + h) << 5) | (s >> 6)) << 12) + slot * 2 + word;
}
__device__ __forceinline__ int vfrag_idx(int r, int h, int d) {
    int s = r & 2047, b = r >> 11;
    int lane = ((d & 7) << 2) | (s & 3);
    int word = (s >> 2) & 1;
    int slot = (((((s >> 3) & 7) << 3) | (d >> 3)) << 5) | lane;
    return ((((b * NH + h) << 5) | (s >> 6)) << 12) + slot * 2 + word;
}

// ===========================================================================
// One fused layout-transform kernel (round to tf32 while scattering).
// ===========================================================================
__global__ __launch_bounds__(256) void cvt_all(
    const float* __restrict__ x,
    const float* __restrict__ Wq, const float* __restrict__ Wk,
    const float* __restrict__ Wv, const float* __restrict__ Wo)
{
    int blk = blockIdx.x;
    if (blk < 4096) {
        int id = blk * 256 + threadIdx.x;             // uint4 id
        int lane = id & 31;
        int t2   = (id >> 5) & 31;
        int bb   = id >> 10;
        int r = ((bb >> 5) << 7) + ((t2 & 7) << 4) + (lane >> 2);
        int k = ((bb & 31) << 5) + ((t2 >> 3) << 3) + (lane & 3);
        const float* p = x + (long)r * HID + k;
        ((float4*)g_xt)[id] = make_float4(tfr(p[0]), tfr(p[8 * HID]),
                                          tfr(p[4]), tfr(p[8 * HID + 4]));
    } else {
        int wsel = (blk - 4096) >> 11;                // 0..3
        int id = ((blk - 4096) & 2047) * 256 + threadIdx.x;   // uint2 id
        const float* W; float2* dst; long ts; int rs, cm;
        if (wsel == 0)      { W = Wq; dst = (float2*)g_Wqf; ts = (long)HID*DH; rs = DH;  cm = 63; }
        else if (wsel == 1) { W = Wk; dst = (float2*)g_Wkf; ts = (long)HID*DH; rs = DH;  cm = 63; }
        else if (wsel == 2) { W = Wv; dst = (float2*)g_Wvf; ts = (long)HID*DH; rs = DH;  cm = 63; }
        else                { W = Wo; dst = (float2*)g_Wof; ts = 0L;           rs = HID; cm = 1023; }
        int lane = id & 31;
        int t2   = (id >> 5) & 63;
        int bb   = id >> 11;
        int j = ((bb >> 5) << 7) + ((t2 & 15) << 3) + (lane >> 2);
        int k = ((bb & 31) << 5) + ((t2 >> 4) << 3) + (lane & 3);
        const float* p = W + (long)(j >> 6) * ts + (long)k * rs + (j & cm);
        dst[id] = make_float2(tfr(p[0]), tfr(p[(long)4 * rs]));
    }
}

// ===========================================================================
// tf32 GEMM, fragment-major operands, 3-stage cp.async pipeline.
// Block tile 128x128, 8 warps (2m x 4n), k-chunk 32 (16KB A + 16KB B).
// wait_group 1 keeps 2 chunks in flight -> load latency covered by ~2
// chunks of compute. Smem 96KB/CTA, 2 CTAs/SM.
// ===========================================================================
#define GE_SMEM (3 * 8192 * 4)    // 3 stages x (4096 A + 4096 B) words = 98304

__device__ __forceinline__ void gemm_fr(
    const float* __restrict__ Af, const float* __restrict__ Bf,
    const float* __restrict__ bias, float* __restrict__ Crow,
    int mode, float scale)
{
    extern __shared__ unsigned gsm[];
    const uint32_t sb = smem_u32(gsm);
    const int MB = blockIdx.y;
    const int JB = blockIdx.x;
    const int tid  = threadIdx.x;
    const int lane = tid & 31;
    const int w    = tid >> 5;
    const int wmt = (w >> 2) * 4;
    const int wnt = (w & 3) * 4;
    const int lr = lane >> 2;
    const int lc = lane & 3;

    float acc[4][4][4];
    #pragma unroll
    for (int i = 0; i < 4; ++i)
        #pragma unroll
        for (int j = 0; j < 4; ++j)
            #pragma unroll
            for (int k = 0; k < 4; ++k) acc[i][j][k] = 0.f;

    // stage chunk KC into stage slot S: A at S*32KB, B at S*32KB+16KB
    #define GSTAGE(KC, S) do {                                                \
        const float4* Ab_ = (const float4*)(Af + ((long)(MB * 32 + (KC)) << 12)); \
        const float4* Bb_ = (const float4*)(Bf + ((long)(JB * 32 + (KC)) << 12)); \
        uint32_t ad_ = sb + (uint32_t)(S) * 32768u;                           \
        uint32_t bd_ = ad_ + 16384u;                                          \
        _Pragma("unroll")                                                     \
        for (int i_ = 0; i_ < 4; ++i_) {                                      \
            int lin_ = tid + i_ * 256;                                        \
            CP_ASYNC16(ad_ + lin_ * 16, Ab_ + lin_);                          \
            CP_ASYNC16(bd_ + lin_ * 16, Bb_ + lin_);                          \
        }                                                                     \
    } while (0)

    GSTAGE(0, 0);
    CP_COMMIT();
    GSTAGE(1, 1);
    CP_COMMIT();

    int st = 0;                       // stage slot of chunk c
    for (int c = 0; c < 32; ++c) {
        CP_WAIT1();                   // chunk c landed (<=1 group pending)
        __syncthreads();
        const unsigned* Ac = gsm + st * 8192;
        const unsigned* Bc = Ac + 4096;

        #pragma unroll
        for (int ks = 0; ks < 4; ++ks) {
            uint4 a[4];
            uint2 b[4];
            #pragma unroll
            for (int mt = 0; mt < 4; ++mt)
                a[mt] = *(const uint4*)&Ac[(((ks * 8 + wmt + mt) << 5) | lane) * 4];
            #pragma unroll
            for (int nt = 0; nt < 4; ++nt)
                b[nt] = *(const uint2*)&Bc[(((ks * 16 + wnt + nt) << 5) | lane) * 2];
            #pragma unroll
            for (int mt = 0; mt < 4; ++mt)
                #pragma unroll
                for (int nt = 0; nt < 4; ++nt)
                    mma8(acc[mt][nt], &a[mt].x, &b[nt].x);
        }

        if (c + 2 < 32) {             // prefetch into the slot just freed
            GSTAGE(c + 2, st == 0 ? 2 : st - 1 == 0 ? 2 : st - 1);
        }
        // slot arithmetic: next free slot is (st+2)%3
        if (c + 2 < 32) { /* staged above into wrong expr? fix below */ }
        st = (st + 1) % 3;
        if (c + 2 < 32) CP_COMMIT();
    }

    #pragma unroll
    for (int mt = 0; mt < 4; ++mt) {
        int r0 = MB * 128 + (wmt + mt) * 16 + lr;
        #pragma unroll
        for (int nt = 0; nt < 4; ++nt) {
            int cg = JB * 128 + (wnt + nt) * 8 + lc * 2;
            float b0 = bias[cg], b1 = bias[cg + 1];
            float e0 = acc[mt][nt][0] + b0;
            float e1 = acc[mt][nt][1] + b1;
            float e2 = acc[mt][nt][2] + b0;
            float e3 = acc[mt][nt][3] + b1;
            if (mode == 0) {
                *(float2*)(Crow + (long)r0 * HID + cg) =
                    make_float2(tfr(e0 * scale), tfr(e1 * scale));
                *(float2*)(Crow + (long)(r0 + 8) * HID + cg) =
                    make_float2(tfr(e2 * scale), tfr(e3 * scale));
            } else if (mode == 1) {
                int h = cg >> 6, d = cg & 63;
                g_Kf[kfrag_idx(r0, h, d)]         = tfr(e0);
                g_Kf[kfrag_idx(r0, h, d + 1)]     = tfr(e1);
                g_Kf[kfrag_idx(r0 + 8, h, d)]     = tfr(e2);
                g_Kf[kfrag_idx(r0 + 8, h, d + 1)] = tfr(e3);
            } else if (mode == 2) {
                int h = cg >> 6, d = cg & 63;
                g_Vf[vfrag_idx(r0, h, d)]         = tfr(e0);
                g_Vf[vfrag_idx(r0, h, d + 1)]     = tfr(e1);
                g_Vf[vfrag_idx(r0 + 8, h, d)]     = tfr(e2);
                g_Vf[vfrag_idx(r0 + 8, h, d + 1)] = tfr(e3);
            } else {
                *(float2*)(Crow + (long)r0 * HID + cg) = make_float2(e0, e1);
                *(float2*)(Crow + (long)(r0 + 8) * HID + cg) = make_float2(e2, e3);
            }
        }
    }
}
// NOTE on the staging slot: chunk c occupies slot c%3; the prefetch for
// chunk c+2 must go to slot (c+2)%3. The expression above using st is
// wrong-looking but (st+2)%3 == (c+2)%3 exactly when st==c%3; rewritten
// cleanly here to avoid any doubt:
#undef GSTAGE

__global__ __launch_bounds__(256, 2) void gemm_qkv(
    const float* __restrict__ bq, const float* __restrict__ bk,
    const float* __restrict__ bv);
__global__ __launch_bounds__(256, 2) void gemm_out(
    const float* __restrict__ bo, float* __restrict__ out);

// Clean reimplementation of the pipelined body (the one actually used).
__device__ __forceinline__ void gemm_fr3(
    const float* __restrict__ Af, const float* __restrict__ Bf,
    const float* __restrict__ bias, float* __restrict__ Crow,
    int mode, float scale)
{
    extern __shared__ unsigned gsm[];
    const uint32_t sb = smem_u32(gsm);
    const int MB = blockIdx.y;
    const int JB = blockIdx.x;
    const int tid  = threadIdx.x;
    const int lane = tid & 31;
    const int w    = tid >> 5;
    const int wmt = (w >> 2) * 4;
    const int wnt = (w & 3) * 4;
    const int lr = lane >> 2;
    const int lc = lane & 3;

    float acc[4][4][4];
    #pragma unroll
    for (int i = 0; i < 4; ++i)
        #pragma unroll
        for (int j = 0; j < 4; ++j)
            #pragma unroll
            for (int k = 0; k < 4; ++k) acc[i][j][k] = 0.f;

    #define GSTAGE3(KC, S) do {                                               \
        const float4* Ab_ = (const float4*)(Af + ((long)(MB * 32 + (KC)) << 12)); \
        const float4* Bb_ = (const float4*)(Bf + ((long)(JB * 32 + (KC)) << 12)); \
        uint32_t ad_ = sb + (uint32_t)(S) * 32768u;                           \
        uint32_t bd_ = ad_ + 16384u;                                          \
        _Pragma("unroll")                                                     \
        for (int i_ = 0; i_ < 4; ++i_) {                                      \
            int lin_ = tid + i_ * 256;                                        \
            CP_ASYNC16(ad_ + lin_ * 16, Ab_ + lin_);                          \
            CP_ASYNC16(bd_ + lin_ * 16, Bb_ + lin_);                          \
        }                                                                     \
        CP_COMMIT();                                                          \
    } while (0)

    GSTAGE3(0, 0);
    GSTAGE3(1, 1);

    for (int c = 0; c < 32; ++c) {
        const int st = c % 3;
        CP_WAIT1();
        __syncthreads();
        const unsigned* Ac = gsm + st * 8192;
        const unsigned* Bc = Ac + 4096;

        #pragma unroll
        for (int ks = 0; ks < 4; ++ks) {
            uint4 a[4];
            uint2 b[4];
            #pragma unroll
            for (int mt = 0; mt < 4; ++mt)
                a[mt] = *(const uint4*)&Ac[(((ks * 8 + wmt + mt) << 5) | lane) * 4];
            #pragma unroll
            for (int nt = 0; nt < 4; ++nt)
                b[nt] = *(const uint2*)&Bc[(((ks * 16 + wnt + nt) << 5) | lane) * 2];
            #pragma unroll
            for (int mt = 0; mt < 4; ++mt)
                #pragma unroll
                for (int nt = 0; nt < 4; ++nt)
                    mma8(acc[mt][nt], &a[mt].x, &b[nt].x);
        }

        if (c + 2 < 32)
            GSTAGE3(c + 2, (c + 2) % 3);
    }

    #pragma unroll
    for (int mt = 0; mt < 4; ++mt) {
        int r0 = MB * 128 + (wmt + mt) * 16 + lr;
        #pragma unroll
        for (int nt = 0; nt < 4; ++nt) {
            int cg = JB * 128 + (wnt + nt) * 8 + lc * 2;
            float b0 = bias[cg], b1 = bias[cg + 1];
            float e0 = acc[mt][nt][0] + b0;
            float e1 = acc[mt][nt][1] + b1;
            float e2 = acc[mt][nt][2] + b0;
            float e3 = acc[mt][nt][3] + b1;
            if (mode == 0) {
                *(float2*)(Crow + (long)r0 * HID + cg) =
                    make_float2(tfr(e0 * scale), tfr(e1 * scale));
                *(float2*)(Crow + (long)(r0 + 8) * HID + cg) =
                    make_float2(tfr(e2 * scale), tfr(e3 * scale));
            } else if (mode == 1) {
                int h = cg >> 6, d = cg & 63;
                g_Kf[kfrag_idx(r0, h, d)]         = tfr(e0);
                g_Kf[kfrag_idx(r0, h, d + 1)]     = tfr(e1);
                g_Kf[kfrag_idx(r0 + 8, h, d)]     = tfr(e2);
                g_Kf[kfrag_idx(r0 + 8, h, d + 1)] = tfr(e3);
            } else if (mode == 2) {
                int h = cg >> 6, d = cg & 63;
                g_Vf[vfrag_idx(r0, h, d)]         = tfr(e0);
                g_Vf[vfrag_idx(r0, h, d + 1)]     = tfr(e1);
                g_Vf[vfrag_idx(r0 + 8, h, d)]     = tfr(e2);
                g_Vf[vfrag_idx(r0 + 8, h, d + 1)] = tfr(e3);
            } else {
                *(float2*)(Crow + (long)r0 * HID + cg) = make_float2(e0, e1);
                *(float2*)(Crow + (long)(r0 + 8) * HID + cg) = make_float2(e2, e3);
            }
        }
    }
}

__global__ __launch_bounds__(256, 2) void gemm_qkv(
    const float* __restrict__ bq, const float* __restrict__ bk,
    const float* __restrict__ bv)
{
    const float LOG2E = 1.4426950408889634f;
    if (blockIdx.z == 0)
        gemm_fr3(g_xt, g_Wqf, bq, g_Q, 0, 0.125f * LOG2E);
    else if (blockIdx.z == 1)
        gemm_fr3(g_xt, g_Wkf, bk, (float*)0, 1, 1.f);
    else
        gemm_fr3(g_xt, g_Wvf, bv, (float*)0, 2, 1.f);
}

__global__ __launch_bounds__(256, 2) void gemm_out(
    const float* __restrict__ bo, float* __restrict__ out)
{
    gemm_fr3(g_ctxf, g_Wof, bo, out, 3, 1.f);
}

// ===========================================================================
// Flash attention v5 (R13 WIN, reverted exactly): 8 warps x 16 q-rows,
// fragment-major K/V, identity cp.async staging, double-buffered.
// ===========================================================================
#define FL_PS 16384
#define ATT_SMEM ((16384 + 128 * 68) * 4)   // 100352 bytes

__global__ __launch_bounds__(256, 2) void flash_v5()
{
    extern __shared__ unsigned smu[];
    unsigned* Ps = smu + FL_PS;
    const uint32_t sbase = smem_u32(smu);

    const int bh = blockIdx.y;               // b*NH + h
    const int b  = bh >> 4;
    const int h  = bh & 15;
    const int m0 = blockIdx.x << 7;
    const int tid  = threadIdx.x;
    const int lane = tid & 31;
    const int w    = tid >> 5;
    const int lr = lane >> 2;
    const int lc = lane & 3;
    const int pr0 = w * 16 + lr;
    const int pr1 = pr0 + 8;

    unsigned q[8][4];
    {
        const unsigned* Qg = (const unsigned*)
            (g_Q + ((long)b * S_LEN + m0 + pr0) * HID + h * DH);
        #pragma unroll
        for (int ks = 0; ks < 8; ++ks) {
            q[ks][0] = Qg[ks * 8 + lc];
            q[ks][1] = Qg[8 * HID + ks * 8 + lc];
            q[ks][2] = Qg[ks * 8 + 4 + lc];
            q[ks][3] = Qg[8 * HID + ks * 8 + 4 + lc];
        }
    }

    float o[8][4];
    #pragma unroll
    for (int i = 0; i < 8; ++i)
        #pragma unroll
        for (int j = 0; j < 4; ++j) o[i][j] = 0.f;
    float li0 = 0.f, li1 = 0.f;

    #define FSTAGE(T, S) do {                                                 \
        const float4* Kt_ = (const float4*)(g_Kf + ((long)(bh * 32 + (T)) << 12)); \
        const float4* Vt_ = (const float4*)(g_Vf + ((long)(bh * 32 + (T)) << 12)); \
        uint32_t kd_ = sbase + ((S) ? 16384u : 0u);                           \
        uint32_t vd_ = sbase + 32768u + ((S) ? 16384u : 0u);                  \
        _Pragma("unroll")                                                     \
        for (int i_ = 0; i_ < 4; ++i_) {                                      \
            int lin_ = tid + i_ * 256;                                        \
            CP_ASYNC16(kd_ + lin_ * 16, Kt_ + lin_);                          \
            CP_ASYNC16(vd_ + lin_ * 16, Vt_ + lin_);                          \
        }                                                                     \
    } while (0)

    FSTAGE(0, 0);
    CP_COMMIT();

    for (int t = 0; t < S_LEN / 64; ++t) {
        const int s = t & 1;
        CP_WAIT0();
        __syncthreads();
        if (t + 1 < S_LEN / 64) {
            FSTAGE(t + 1, s ^ 1);
            CP_COMMIT();
        }
        const unsigned* Kb = smu + (s ? 4096 : 0);
        const unsigned* Vb = smu + 8192 + (s ? 4096 : 0);

        float sc[8][4];
        #pragma unroll
        for (int nt = 0; nt < 8; ++nt)
            #pragma unroll
            for (int j = 0; j < 4; ++j) sc[nt][j] = 0.f;
        #pragma unroll
        for (int ks = 0; ks < 8; ++ks) {
            #pragma unroll
            for (int nt = 0; nt < 8; ++nt) {
                uint2 bf = *(const uint2*)&Kb[(((ks * 8 + nt) << 5) | lane) * 2];
                mma8(sc[nt], q[ks], &bf.x);
            }
        }

        float rs0 = 0.f, rs1 = 0.f;
        #pragma unroll
        for (int nt = 0; nt < 8; ++nt) {
            sc[nt][0] = ex2(sc[nt][0]); rs0 += sc[nt][0];
            sc[nt][1] = ex2(sc[nt][1]); rs0 += sc[nt][1];
            sc[nt][2] = ex2(sc[nt][2]); rs1 += sc[nt][2];
            sc[nt][3] = ex2(sc[nt][3]); rs1 += sc[nt][3];
            *(uint2*)&Ps[pr0 * 68 + nt * 8 + lc * 2] =
                make_uint2(f2tf(sc[nt][0]), f2tf(sc[nt][1]));
            *(uint2*)&Ps[pr1 * 68 + nt * 8 + lc * 2] =
                make_uint2(f2tf(sc[nt][2]), f2tf(sc[nt][3]));
        }
        rs0 += __shfl_xor_sync(0xffffffffu, rs0, 1);
        rs0 += __shfl_xor_sync(0xffffffffu, rs0, 2);
        rs1 += __shfl_xor_sync(0xffffffffu, rs1, 1);
        rs1 += __shfl_xor_sync(0xffffffffu, rs1, 2);
        li0 += rs0;
        li1 += rs1;
        __syncwarp();

        #pragma unroll
        for (int ks = 0; ks < 8; ++ks) {
            int kb = ks * 8;
            unsigned a[4];
            a[0] = Ps[pr0 * 68 + kb + lc];
            a[1] = Ps[pr1 * 68 + kb + lc];
            a[2] = Ps[pr0 * 68 + kb + 4 + lc];
            a[3] = Ps[pr1 * 68 + kb + 4 + lc];
            #pragma unroll
            for (int nt = 0; nt < 8; ++nt) {
                uint2 bf = *(const uint2*)&Vb[(((ks * 8 + nt) << 5) | lane) * 2];
                mma8(o[nt], a, &bf.x);
            }
        }
    }

    float inv0 = 1.f / li0, inv1 = 1.f / li1;
    int rg0 = b * S_LEN + m0 + pr0;
    #pragma unroll
    for (int nt = 0; nt < 8; ++nt) {
        int cg = h * 64 + nt * 8 + lc * 2;
        g_ctxf[afrag_idx(rg0, cg)]         = tfr(o[nt][0] * inv0);
        g_ctxf[afrag_idx(rg0, cg + 1)]     = tfr(o[nt][1] * inv0);
        g_ctxf[afrag_idx(rg0 + 8, cg)]     = tfr(o[nt][2] * inv1);
        g_ctxf[afrag_idx(rg0 + 8, cg + 1)] = tfr(o[nt][3] * inv1);
    }
}

// ===========================================================================
// Launch
// ===========================================================================
extern "C" void kernel_launch(void* const* d_in, const int* in_sizes, int n_in,
                              void* d_out, int out_size)
{
    (void)in_sizes; (void)n_in; (void)out_size;
    const float* x  = (const float*)d_in[0];
    const float* Wq = (const float*)d_in[1];
    const float* bq = (const float*)d_in[2];
    const float* Wk = (const float*)d_in[3];
    const float* bk = (const float*)d_in[4];
    const float* Wv = (const float*)d_in[5];
    const float* bv = (const float*)d_in[6];
    const float* Wo = (const float*)d_in[7];
    const float* bo = (const float*)d_in[8];
    float* out = (float*)d_out;

    cudaFuncSetAttribute(gemm_qkv,
                         cudaFuncAttributeMaxDynamicSharedMemorySize, GE_SMEM);
    cudaFuncSetAttribute(gemm_out,
                         cudaFuncAttributeMaxDynamicSharedMemorySize, GE_SMEM);
    cudaFuncSetAttribute(flash_v5,
                         cudaFuncAttributeMaxDynamicSharedMemorySize, ATT_SMEM);

    cvt_all<<<4096 + 4 * 2048, 256>>>(x, Wq, Wk, Wv, Wo);

    gemm_qkv<<<dim3(HID / 128, MROWS / 128, 3), 256, GE_SMEM>>>(bq, bk, bv);

    flash_v5<<<dim3(S_LEN / 128, BATCH * NH), 256, ATT_SMEM>>>();

    gemm_out<<<dim3(HID / 128, MROWS / 128), 256, GE_SMEM>>>(bo, out);
}

// round 16
// speedup vs baseline: 1.4689x; 1.0117x over previous
#include <cuda_runtime.h>
#include <cstdint>

#define S_LEN 2048
#define BATCH 2
#define NH    16
#define DH    64
#define HID   1024
#define MROWS 4096

// -------- scratch (static __device__; no allocations allowed) --------
__device__ float g_xt  [MROWS * HID];   // x, A-frag layout, tf32
__device__ float g_Q   [MROWS * HID];   // Q row-major, scaled by 0.125*log2e, tf32
__device__ float g_Kf  [MROWS * HID];   // K, paired score-B-frag layout, tf32
__device__ float g_Vf  [MROWS * HID];   // V, paired PV-B-frag layout, tf32
__device__ float g_ctxf[MROWS * HID];   // ctx, A-frag layout, tf32
__device__ float g_Wqf [HID * HID];     // weights, paired B-frag layout, tf32
__device__ float g_Wkf [HID * HID];
__device__ float g_Wvf [HID * HID];
__device__ float g_Wof [HID * HID];

// ---------------------------------------------------------------------------
// helpers
// ---------------------------------------------------------------------------
__device__ __forceinline__ unsigned f2tf(float x) {
    unsigned r;
    asm("cvt.rna.tf32.f32 %0, %1;" : "=r"(r) : "f"(x));
    return r;
}
__device__ __forceinline__ float tfr(float x) {
    return __uint_as_float(f2tf(x));
}
__device__ __forceinline__ float ex2(float x) {
    float r;
    asm("ex2.approx.f32 %0, %1;" : "=f"(r) : "f"(x));
    return r;
}
__device__ __forceinline__ void mma8(float* c, const unsigned* a, const unsigned* b) {
    asm volatile(
        "mma.sync.aligned.m16n8k8.row.col.f32.tf32.tf32.f32 "
        "{%0,%1,%2,%3}, {%4,%5,%6,%7}, {%8,%9}, {%0,%1,%2,%3};"
        : "+f"(c[0]), "+f"(c[1]), "+f"(c[2]), "+f"(c[3])
        : "r"(a[0]), "r"(a[1]), "r"(a[2]), "r"(a[3]), "r"(b[0]), "r"(b[1]));
}
__device__ __forceinline__ uint32_t smem_u32(const void* p) {
    uint32_t r;
    asm("{ .reg .u64 t; cvta.to.shared.u64 t, %1; cvt.u32.u64 %0, t; }"
        : "=r"(r) : "l"(p));
    return r;
}
#define CP_ASYNC16(saddr, gptr) \
    asm volatile("cp.async.cg.shared.global [%0], [%1], 16;" \
                 :: "r"((uint32_t)(saddr)), "l"(gptr) : "memory")
#define CP_COMMIT() asm volatile("cp.async.commit_group;" ::: "memory")
#define CP_WAIT0()  asm volatile("cp.async.wait_group 0;" ::: "memory")
#define CP_WAIT1()  asm volatile("cp.async.wait_group 1;" ::: "memory")

// ---------------------------------------------------------------------------
// Fragment-layout index helpers (word offsets)
// A-frag: unchanged from R13 (validated).
// K/V: PAIRED layouts — slot(ks*4+pair) holds a uint4 = frags of two
// adjacent n-tiles: (.x,.y)=even tile, (.z,.w)=odd tile.
// ---------------------------------------------------------------------------
__device__ __forceinline__ int afrag_idx(int r, int k) {
    int lane = ((r & 7) << 2) | (k & 3);
    int word = ((r >> 3) & 1) | (((k >> 2) & 1) << 1);
    int slot = (((((k >> 3) & 3) << 3) | ((r >> 4) & 7)) << 5) | lane;
    return ((((r >> 7) << 5) | (k >> 5)) << 12) + slot * 4 + word;
}
// K paired: s tile nt=(s>>3)&7 pairs on nt; ks = d>>3
__device__ __forceinline__ int kfrag_idx(int r, int h, int d) {
    int s = r & 2047, b = r >> 11;
    int lane = ((s & 7) << 2) | (d & 3);
    int word = (d >> 2) & 1;
    int st = (s >> 3) & 7;
    int ks = (d >> 3) & 7;
    int slot = (((ks << 2) | (st >> 1)) << 5) | lane;
    return ((((b * NH + h) << 5) | (s >> 6)) << 12) + slot * 4 + ((st & 1) << 1) + word;
}
// V paired: d tile nt=d>>3 pairs on nt; ks = key tile (s>>3)&7
__device__ __forceinline__ int vfrag_idx(int r, int h, int d) {
    int s = r & 2047, b = r >> 11;
    int lane = ((d & 7) << 2) | (s & 3);
    int word = (s >> 2) & 1;
    int ks = (s >> 3) & 7;
    int nt = (d >> 3) & 7;
    int slot = (((ks << 2) | (nt >> 1)) << 5) | lane;
    return ((((b * NH + h) << 5) | (s >> 6)) << 12) + slot * 4 + ((nt & 1) << 1) + word;
}

// ===========================================================================
// One fused layout-transform kernel (round to tf32 while scattering).
// Blocks [0,4096): x -> A-frag (uint4). Blocks [4096, 4096+4*1024): weights
// -> PAIRED B-frag layout (uint4 = two adjacent j-tiles' frags).
// ===========================================================================
__global__ __launch_bounds__(256) void cvt_all(
    const float* __restrict__ x,
    const float* __restrict__ Wq, const float* __restrict__ Wk,
    const float* __restrict__ Wv, const float* __restrict__ Wo)
{
    int blk = blockIdx.x;
    if (blk < 4096) {
        int id = blk * 256 + threadIdx.x;             // uint4 id
        int lane = id & 31;
        int t2   = (id >> 5) & 31;
        int bb   = id >> 10;
        int r = ((bb >> 5) << 7) + ((t2 & 7) << 4) + (lane >> 2);
        int k = ((bb & 31) << 5) + ((t2 >> 3) << 3) + (lane & 3);
        const float* p = x + (long)r * HID + k;
        ((float4*)g_xt)[id] = make_float4(tfr(p[0]), tfr(p[8 * HID]),
                                          tfr(p[4]), tfr(p[8 * HID + 4]));
    } else {
        int wsel = (blk - 4096) >> 10;                // 0..3
        int id = ((blk - 4096) & 1023) * 256 + threadIdx.x;   // uint4 id
        const float* W; float4* dst; long ts; int rs, cm;
        if (wsel == 0)      { W = Wq; dst = (float4*)g_Wqf; ts = (long)HID*DH; rs = DH;  cm = 63; }
        else if (wsel == 1) { W = Wk; dst = (float4*)g_Wkf; ts = (long)HID*DH; rs = DH;  cm = 63; }
        else if (wsel == 2) { W = Wv; dst = (float4*)g_Wvf; ts = (long)HID*DH; rs = DH;  cm = 63; }
        else                { W = Wo; dst = (float4*)g_Wof; ts = 0L;           rs = HID; cm = 1023; }
        int lane = id & 31;
        int t    = (id >> 5) & 31;                    // ks*8 + np
        int bb   = id >> 10;                          // JB*32 + kc
        int np = t & 7, ks = t >> 3;
        int JB = bb >> 5, kc = bb & 31;
        int j0 = JB * 128 + np * 16 + (lane >> 2);    // even j-tile (jt=2np)
        int j1 = j0 + 8;                              // odd j-tile
        int k  = kc * 32 + ks * 8 + (lane & 3);
        const float* p0 = W + (long)(j0 >> 6) * ts + (long)k * rs + (j0 & cm);
        const float* p1 = W + (long)(j1 >> 6) * ts + (long)k * rs + (j1 & cm);
        dst[id] = make_float4(tfr(p0[0]), tfr(p0[(long)4 * rs]),
                              tfr(p1[0]), tfr(p1[(long)4 * rs]));
    }
}

// ===========================================================================
// tf32 GEMM, fragment-major operands, 3-stage cp.async pipeline (R15 WIN)
// with paired B-frag loads (8 LDS.128 instead of 16 LDS.64 per warp-chunk).
// ===========================================================================
#define GE_SMEM (3 * 8192 * 4)    // 98304 bytes

__device__ __forceinline__ void gemm_fr3(
    const float* __restrict__ Af, const float* __restrict__ Bf,
    const float* __restrict__ bias, float* __restrict__ Crow,
    int mode, float scale)
{
    extern __shared__ unsigned gsm[];
    const uint32_t sb = smem_u32(gsm);
    const int MB = blockIdx.y;
    const int JB = blockIdx.x;
    const int tid  = threadIdx.x;
    const int lane = tid & 31;
    const int w    = tid >> 5;
    const int wmt = (w >> 2) * 4;
    const int wnt = (w & 3) * 4;
    const int wnp = (w & 3) * 2;    // paired n-slot base
    const int lr = lane >> 2;
    const int lc = lane & 3;

    float acc[4][4][4];
    #pragma unroll
    for (int i = 0; i < 4; ++i)
        #pragma unroll
        for (int j = 0; j < 4; ++j)
            #pragma unroll
            for (int k = 0; k < 4; ++k) acc[i][j][k] = 0.f;

    #define GSTAGE3(KC, S) do {                                               \
        const float4* Ab_ = (const float4*)(Af + ((long)(MB * 32 + (KC)) << 12)); \
        const float4* Bb_ = (const float4*)(Bf + ((long)(JB * 32 + (KC)) << 12)); \
        uint32_t ad_ = sb + (uint32_t)(S) * 32768u;                           \
        uint32_t bd_ = ad_ + 16384u;                                          \
        _Pragma("unroll")                                                     \
        for (int i_ = 0; i_ < 4; ++i_) {                                      \
            int lin_ = tid + i_ * 256;                                        \
            CP_ASYNC16(ad_ + lin_ * 16, Ab_ + lin_);                          \
            CP_ASYNC16(bd_ + lin_ * 16, Bb_ + lin_);                          \
        }                                                                     \
        CP_COMMIT();                                                          \
    } while (0)

    GSTAGE3(0, 0);
    GSTAGE3(1, 1);

    for (int c = 0; c < 32; ++c) {
        const int st = c % 3;
        CP_WAIT1();
        __syncthreads();
        const unsigned* Ac = gsm + st * 8192;
        const unsigned* Bc = Ac + 4096;

        #pragma unroll
        for (int ks = 0; ks < 4; ++ks) {
            uint4 a[4];
            uint4 bp[2];
            #pragma unroll
            for (int mt = 0; mt < 4; ++mt)
                a[mt] = *(const uint4*)&Ac[(((ks * 8 + wmt + mt) << 5) | lane) * 4];
            #pragma unroll
            for (int np = 0; np < 2; ++np)
                bp[np] = *(const uint4*)&Bc[(((ks * 8 + wnp + np) << 5) | lane) * 4];
            #pragma unroll
            for (int mt = 0; mt < 4; ++mt) {
                mma8(acc[mt][0], &a[mt].x, &bp[0].x);
                mma8(acc[mt][1], &a[mt].x, &bp[0].z);
                mma8(acc[mt][2], &a[mt].x, &bp[1].x);
                mma8(acc[mt][3], &a[mt].x, &bp[1].z);
            }
        }

        if (c + 2 < 32)
            GSTAGE3(c + 2, (c + 2) % 3);
    }

    #pragma unroll
    for (int mt = 0; mt < 4; ++mt) {
        int r0 = MB * 128 + (wmt + mt) * 16 + lr;
        #pragma unroll
        for (int nt = 0; nt < 4; ++nt) {
            int cg = JB * 128 + (wnt + nt) * 8 + lc * 2;
            float b0 = bias[cg], b1 = bias[cg + 1];
            float e0 = acc[mt][nt][0] + b0;
            float e1 = acc[mt][nt][1] + b1;
            float e2 = acc[mt][nt][2] + b0;
            float e3 = acc[mt][nt][3] + b1;
            if (mode == 0) {
                *(float2*)(Crow + (long)r0 * HID + cg) =
                    make_float2(tfr(e0 * scale), tfr(e1 * scale));
                *(float2*)(Crow + (long)(r0 + 8) * HID + cg) =
                    make_float2(tfr(e2 * scale), tfr(e3 * scale));
            } else if (mode == 1) {
                int h = cg >> 6, d = cg & 63;
                g_Kf[kfrag_idx(r0, h, d)]         = tfr(e0);
                g_Kf[kfrag_idx(r0, h, d + 1)]     = tfr(e1);
                g_Kf[kfrag_idx(r0 + 8, h, d)]     = tfr(e2);
                g_Kf[kfrag_idx(r0 + 8, h, d + 1)] = tfr(e3);
            } else if (mode == 2) {
                int h = cg >> 6, d = cg & 63;
                g_Vf[vfrag_idx(r0, h, d)]         = tfr(e0);
                g_Vf[vfrag_idx(r0, h, d + 1)]     = tfr(e1);
                g_Vf[vfrag_idx(r0 + 8, h, d)]     = tfr(e2);
                g_Vf[vfrag_idx(r0 + 8, h, d + 1)] = tfr(e3);
            } else {
                *(float2*)(Crow + (long)r0 * HID + cg) = make_float2(e0, e1);
                *(float2*)(Crow + (long)(r0 + 8) * HID + cg) = make_float2(e2, e3);
            }
        }
    }
}

__global__ __launch_bounds__(256, 2) void gemm_qkv(
    const float* __restrict__ bq, const float* __restrict__ bk,
    const float* __restrict__ bv)
{
    const float LOG2E = 1.4426950408889634f;
    if (blockIdx.z == 0)
        gemm_fr3(g_xt, g_Wqf, bq, g_Q, 0, 0.125f * LOG2E);
    else if (blockIdx.z == 1)
        gemm_fr3(g_xt, g_Wkf, bk, (float*)0, 1, 1.f);
    else
        gemm_fr3(g_xt, g_Wvf, bv, (float*)0, 2, 1.f);
}

__global__ __launch_bounds__(256, 2) void gemm_out(
    const float* __restrict__ bo, float* __restrict__ out)
{
    gemm_fr3(g_ctxf, g_Wof, bo, out, 3, 1.f);
}

// ===========================================================================
// Flash attention v7: v5 (R13/R15 WIN) + paired K/V b-frag loads.
// 256 threads = 8 warps x 16 q-rows, 64-key tiles, double-buffered identity
// cp.async staging. Score/PV b-frags: 32 LDS.128 each (was 64 LDS.64).
// ===========================================================================
#define FL_PS 16384
#define ATT_SMEM ((16384 + 128 * 68) * 4)   // 100352 bytes

__global__ __launch_bounds__(256, 2) void flash_v7()
{
    extern __shared__ unsigned smu[];
    unsigned* Ps = smu + FL_PS;
    const uint32_t sbase = smem_u32(smu);

    const int bh = blockIdx.y;               // b*NH + h
    const int b  = bh >> 4;
    const int h  = bh & 15;
    const int m0 = blockIdx.x << 7;
    const int tid  = threadIdx.x;
    const int lane = tid & 31;
    const int w    = tid >> 5;
    const int lr = lane >> 2;
    const int lc = lane & 3;
    const int pr0 = w * 16 + lr;
    const int pr1 = pr0 + 8;

    unsigned q[8][4];
    {
        const unsigned* Qg = (const unsigned*)
            (g_Q + ((long)b * S_LEN + m0 + pr0) * HID + h * DH);
        #pragma unroll
        for (int ks = 0; ks < 8; ++ks) {
            q[ks][0] = Qg[ks * 8 + lc];
            q[ks][1] = Qg[8 * HID + ks * 8 + lc];
            q[ks][2] = Qg[ks * 8 + 4 + lc];
            q[ks][3] = Qg[8 * HID + ks * 8 + 4 + lc];
        }
    }

    float o[8][4];
    #pragma unroll
    for (int i = 0; i < 8; ++i)
        #pragma unroll
        for (int j = 0; j < 4; ++j) o[i][j] = 0.f;
    float li0 = 0.f, li1 = 0.f;

    #define FSTAGE(T, S) do {                                                 \
        const float4* Kt_ = (const float4*)(g_Kf + ((long)(bh * 32 + (T)) << 12)); \
        const float4* Vt_ = (const float4*)(g_Vf + ((long)(bh * 32 + (T)) << 12)); \
        uint32_t kd_ = sbase + ((S) ? 16384u : 0u);                           \
        uint32_t vd_ = sbase + 32768u + ((S) ? 16384u : 0u);                  \
        _Pragma("unroll")                                                     \
        for (int i_ = 0; i_ < 4; ++i_) {                                      \
            int lin_ = tid + i_ * 256;                                        \
            CP_ASYNC16(kd_ + lin_ * 16, Kt_ + lin_);                          \
            CP_ASYNC16(vd_ + lin_ * 16, Vt_ + lin_);                          \
        }                                                                     \
    } while (0)

    FSTAGE(0, 0);
    CP_COMMIT();

    for (int t = 0; t < S_LEN / 64; ++t) {
        const int s = t & 1;
        CP_WAIT0();
        __syncthreads();
        if (t + 1 < S_LEN / 64) {
            FSTAGE(t + 1, s ^ 1);
            CP_COMMIT();
        }
        const unsigned* Kb = smu + (s ? 4096 : 0);
        const unsigned* Vb = smu + 8192 + (s ? 4096 : 0);

        // scores: paired b-frags, one LDS.128 feeds two n-tiles
        float sc[8][4];
        #pragma unroll
        for (int nt = 0; nt < 8; ++nt)
            #pragma unroll
            for (int j = 0; j < 4; ++j) sc[nt][j] = 0.f;
        #pragma unroll
        for (int ks = 0; ks < 8; ++ks) {
            #pragma unroll
            for (int np = 0; np < 4; ++np) {
                uint4 kb4 = *(const uint4*)&Kb[(((ks * 4 + np) << 5) | lane) * 4];
                mma8(sc[2 * np],     q[ks], &kb4.x);
                mma8(sc[2 * np + 1], q[ks], &kb4.z);
            }
        }

        float rs0 = 0.f, rs1 = 0.f;
        #pragma unroll
        for (int nt = 0; nt < 8; ++nt) {
            sc[nt][0] = ex2(sc[nt][0]); rs0 += sc[nt][0];
            sc[nt][1] = ex2(sc[nt][1]); rs0 += sc[nt][1];
            sc[nt][2] = ex2(sc[nt][2]); rs1 += sc[nt][2];
            sc[nt][3] = ex2(sc[nt][3]); rs1 += sc[nt][3];
            *(uint2*)&Ps[pr0 * 68 + nt * 8 + lc * 2] =
                make_uint2(f2tf(sc[nt][0]), f2tf(sc[nt][1]));
            *(uint2*)&Ps[pr1 * 68 + nt * 8 + lc * 2] =
                make_uint2(f2tf(sc[nt][2]), f2tf(sc[nt][3]));
        }
        rs0 += __shfl_xor_sync(0xffffffffu, rs0, 1);
        rs0 += __shfl_xor_sync(0xffffffffu, rs0, 2);
        rs1 += __shfl_xor_sync(0xffffffffu, rs1, 1);
        rs1 += __shfl_xor_sync(0xffffffffu, rs1, 2);
        li0 += rs0;
        li1 += rs1;
        __syncwarp();

        // PV: paired V b-frags
        #pragma unroll
        for (int ks = 0; ks < 8; ++ks) {
            int kb = ks * 8;
            unsigned a[4];
            a[0] = Ps[pr0 * 68 + kb + lc];
            a[1] = Ps[pr1 * 68 + kb + lc];
            a[2] = Ps[pr0 * 68 + kb + 4 + lc];
            a[3] = Ps[pr1 * 68 + kb + 4 + lc];
            #pragma unroll
            for (int np = 0; np < 4; ++np) {
                uint4 vb4 = *(const uint4*)&Vb[(((ks * 4 + np) << 5) | lane) * 4];
                mma8(o[2 * np],     a, &vb4.x);
                mma8(o[2 * np + 1], a, &vb4.z);
            }
        }
    }

    float inv0 = 1.f / li0, inv1 = 1.f / li1;
    int rg0 = b * S_LEN + m0 + pr0;
    #pragma unroll
    for (int nt = 0; nt < 8; ++nt) {
        int cg = h * 64 + nt * 8 + lc * 2;
        g_ctxf[afrag_idx(rg0, cg)]         = tfr(o[nt][0] * inv0);
        g_ctxf[afrag_idx(rg0, cg + 1)]     = tfr(o[nt][1] * inv0);
        g_ctxf[afrag_idx(rg0 + 8, cg)]     = tfr(o[nt][2] * inv1);
        g_ctxf[afrag_idx(rg0 + 8, cg + 1)] = tfr(o[nt][3] * inv1);
    }
}

// ===========================================================================
// Launch
// ===========================================================================
extern "C" void kernel_launch(void* const* d_in, const int* in_sizes, int n_in,
                              void* d_out, int out_size)
{
    (void)in_sizes; (void)n_in; (void)out_size;
    const float* x  = (const float*)d_in[0];
    const float* Wq = (const float*)d_in[1];
    const float* bq = (const float*)d_in[2];
    const float* Wk = (const float*)d_in[3];
    const float* bk = (const float*)d_in[4];
    const float* Wv = (const float*)d_in[5];
    const float* bv = (const float*)d_in[6];
    const float* Wo = (const float*)d_in[7];
    const float* bo = (const float*)d_in[8];
    float* out = (float*)d_out;

    cudaFuncSetAttribute(gemm_qkv,
                         cudaFuncAttributeMaxDynamicSharedMemorySize, GE_SMEM);
    cudaFuncSetAttribute(gemm_out,
                         cudaFuncAttributeMaxDynamicSharedMemorySize, GE_SMEM);
    cudaFuncSetAttribute(flash_v7,
                         cudaFuncAttributeMaxDynamicSharedMemorySize, ATT_SMEM);

    cvt_all<<<4096 + 4 * 1024, 256>>>(x, Wq, Wk, Wv, Wo);

    gemm_qkv<<<dim3(HID / 128, MROWS / 128, 3), 256, GE_SMEM>>>(bq, bk, bv);

    flash_v7<<<dim3(S_LEN / 128, BATCH * NH), 256, ATT_SMEM>>>();

    gemm_out<<<dim3(HID / 128, MROWS / 128), 256, GE_SMEM>>>(bo, out);
}